// round 16
// baseline (speedup 1.0000x reference)
#include <cuda_runtime.h>
#include <cuda_bf16.h>
#include <cstdint>

// Problem constants (shapes fixed by setup_inputs)
#define HW      (1024 * 1024)             // pixels per channel
#define NBINS   16
#define NTOT    (NBINS * NBINS * NBINS)   // 4096
#define NPAIR   (NTOT / 2)                // 2048 paired (64-bit) bins
#define NIMG    9                         // 8 input images + 1 style image
#define BPI     128                       // blocks per image
#define TPB     256                       // threads per block
#define NCTA    (BPI * NIMG)              // 1152 CTAs (single wave @ 8/SM)

// Global scratch (zero-initialized at module load; the last CTA re-zeros it
// each run, so every graph replay sees clean state).
__device__ unsigned long long g_hist2[NIMG][NPAIR];
__device__ unsigned int       g_done;     // ticket for last-CTA detection

// Skewed shared-memory layout: rotate the low-5-bit lane (bank) by the row
// index so that the Gaussian-hot corner bins spread across banks instead of
// piling onto banks {0,15,16,31}. Bijective within each 32-entry row.
__device__ __forceinline__ int skew(int f) {
    return (f & ~31) | ((f + (f >> 5)) & 31);
}

// searchsorted(boundaries, v, side='left') with boundaries = i/8 - 1, i=1..15.
// = count of boundaries strictly < v = clamp(ceil(8*(v+1)) - 1, 0, 15).
__device__ __forceinline__ int bin_of(float v) {
    int i = __float2int_ru(fmaf(v, 8.0f, 8.0f)) - 1;   // single F2I.CEIL
    i = max(i, 0);
    i = min(i, 15);
    return i;
}

__device__ __forceinline__ int flat_bin(float r, float g, float b) {
    return bin_of(r) + (bin_of(g) << 4) + (bin_of(b) << 8);
}

// One acq_rel RMW per CTA instead of 256 MEMBAR.ALL.GPU per CTA.
// Release orders this CTA's prior (bar.sync-collected) flush atomics;
// the RMW chain forms a release sequence, so the CTA that reads
// ticket == NCTA-1 with acquire synchronizes with ALL CTAs' flushes.
__device__ __forceinline__ unsigned int ticket_acq_rel(unsigned int* addr) {
    unsigned int old;
    asm volatile("atom.acq_rel.gpu.add.u32 %0, [%1], %2;"
                 : "=r"(old) : "l"(addr), "r"(1u) : "memory");
    return old;
}

// ---------------------------------------------------------------------------
// Fused kernel: histogram (round-8 config, at its ATOMS floor) + last-CTA
// loss epilogue gated by a single release/acquire ticket per CTA.
// grid = (BPI, NIMG), block = TPB.
// ---------------------------------------------------------------------------
__global__ __launch_bounds__(TPB) void fused_colorloss_kernel(
    const float* __restrict__ inp,   // [8, 3, H, W]
    const float* __restrict__ sty,   // [1, 3, H, W]
    float* __restrict__ out)         // [1]
{
    __shared__ int sh[NTOT];         // 16 KB per-CTA histogram (skewed)
    #pragma unroll
    for (int i = threadIdx.x; i < NTOT; i += TPB) sh[i] = 0;
    __syncthreads();

    const int img = blockIdx.y;
    const float* base = (img < 8) ? (inp + (size_t)img * 3 * HW) : sty;

    const float4* r4 = (const float4*)(base);
    const float4* g4 = (const float4*)(base + HW);
    const float4* b4 = (const float4*)(base + 2 * HW);

    const int per_block = (HW / 4) / BPI;          // 2048 float4 per channel
    const int start     = blockIdx.x * per_block;
    const int end       = start + per_block;

    // 6 front-batched LDG.128 per iteration for explicit MLP, then 8 atomics.
    for (int i = start + threadIdx.x; i < end; i += 2 * TPB) {
        float4 ra = r4[i];
        float4 rb = r4[i + TPB];
        float4 ga = g4[i];
        float4 gb = g4[i + TPB];
        float4 ba = b4[i];
        float4 bb = b4[i + TPB];

        atomicAdd(&sh[skew(flat_bin(ra.x, ga.x, ba.x))], 1);
        atomicAdd(&sh[skew(flat_bin(ra.y, ga.y, ba.y))], 1);
        atomicAdd(&sh[skew(flat_bin(ra.z, ga.z, ba.z))], 1);
        atomicAdd(&sh[skew(flat_bin(ra.w, ga.w, ba.w))], 1);
        atomicAdd(&sh[skew(flat_bin(rb.x, gb.x, bb.x))], 1);
        atomicAdd(&sh[skew(flat_bin(rb.y, gb.y, bb.y))], 1);
        atomicAdd(&sh[skew(flat_bin(rb.z, gb.z, bb.z))], 1);
        atomicAdd(&sh[skew(flat_bin(rb.w, gb.w, bb.w))], 1);
    }
    __syncthreads();

    // Flush: unskew, pack two adjacent f-bins into one 64-bit atomic.
    #pragma unroll
    for (int fp = threadIdx.x; fp < NPAIR; fp += TPB) {
        unsigned int lo = (unsigned int)sh[skew(2 * fp)];
        unsigned int hi = (unsigned int)sh[skew(2 * fp + 1)];
        if (lo | hi) {
            atomicAdd(&g_hist2[img][fp],
                      (unsigned long long)lo | ((unsigned long long)hi << 32));
        }
    }

    // --- last-CTA detection: bar.sync + ONE acq_rel ticket (no MEMBAR storm)
    __syncthreads();                 // collects all threads' flush atomics
    __shared__ int is_last;
    if (threadIdx.x == 0) {
        unsigned int ticket = ticket_acq_rel(&g_done);
        is_last = (ticket == (unsigned int)(NCTA - 1));
    }
    __syncthreads();                 // broadcasts is_last; block-scope order
    if (!is_last) return;

    // --- last CTA: exact integer L1 loss over all 2048 pairs ---
    // Each thread owns 8 pair indices; 9 independent __ldcg loads each
    // (L2-coherent with the REDG-written data; bypasses possibly-stale L1).
    int acc = 0;   // max possible sum = 2*8*HW = 16.8M < 2^31
    #pragma unroll
    for (int k = 0; k < NPAIR / TPB; k++) {
        const int i = k * TPB + threadIdx.x;

        unsigned long long ps = __ldcg(&g_hist2[8][i]);
        unsigned long long p0 = __ldcg(&g_hist2[0][i]);
        unsigned long long p1 = __ldcg(&g_hist2[1][i]);
        unsigned long long p2 = __ldcg(&g_hist2[2][i]);
        unsigned long long p3 = __ldcg(&g_hist2[3][i]);
        unsigned long long p4 = __ldcg(&g_hist2[4][i]);
        unsigned long long p5 = __ldcg(&g_hist2[5][i]);
        unsigned long long p6 = __ldcg(&g_hist2[6][i]);
        unsigned long long p7 = __ldcg(&g_hist2[7][i]);

        int slo = (int)(unsigned int)ps;
        int shi = (int)(unsigned int)(ps >> 32);

        #define ABS_DIFF(p) do {                                  \
            int d0 = (int)(unsigned int)(p) - slo;                \
            int d1 = (int)(unsigned int)((p) >> 32) - shi;        \
            acc += (d0 < 0 ? -d0 : d0) + (d1 < 0 ? -d1 : d1);     \
        } while (0)
        ABS_DIFF(p0); ABS_DIFF(p1); ABS_DIFF(p2); ABS_DIFF(p3);
        ABS_DIFF(p4); ABS_DIFF(p5); ABS_DIFF(p6); ABS_DIFF(p7);
        #undef ABS_DIFF

        // reset this slice of scratch for the next graph replay
        #pragma unroll
        for (int b = 0; b < NIMG; b++) g_hist2[b][i] = 0ULL;
    }

    // block reduction
    #pragma unroll
    for (int o = 16; o > 0; o >>= 1)
        acc += __shfl_xor_sync(0xffffffffu, acc, o);

    __shared__ int warp_sum[TPB / 32];
    if ((threadIdx.x & 31) == 0) warp_sum[threadIdx.x >> 5] = acc;
    __syncthreads();

    if (threadIdx.x == 0) {
        long long total = 0;
        #pragma unroll
        for (int w = 0; w < TPB / 32; w++) total += warp_sum[w];
        out[0] = (float)((double)total /
                         ((double)HW * 8.0 * (double)NTOT));
        g_done = 0u;   // reset ticket for next replay
    }
}

// ---------------------------------------------------------------------------
// Launch contract
// ---------------------------------------------------------------------------
extern "C" void kernel_launch(void* const* d_in, const int* in_sizes, int n_in,
                              void* d_out, int out_size)
{
    const float* inp = (const float*)d_in[0];   // [8,3,1024,1024] fp32
    const float* sty = (const float*)d_in[1];   // [1,3,1024,1024] fp32
    float* out = (float*)d_out;

    dim3 grid(BPI, NIMG);
    fused_colorloss_kernel<<<grid, TPB>>>(inp, sty, out);
}